// round 4
// baseline (speedup 1.0000x reference)
#include <cuda_runtime.h>

#define NNODES 25000
#define CMSG   200
#define EMAX   400000

// ---------------- scratch (no allocation allowed -> device globals) ----------
static __device__ float g_xr[NNODES * 20];        // relu'd layer input (for x_i - x_j)
static __device__ float g_pi[NNODES * CMSG];      // pre_i = x@Wm1_top + bm1   (20 MB)
static __device__ float g_pj[NNODES * CMSG];      // pre_j = x@Wm1_bot         (20 MB)
static __device__ float g_bufA[NNODES * 20];
static __device__ float g_bufB[NNODES * 20];
static __device__ int   g_src[EMAX];
static __device__ int   g_dst[EMAX];
static __device__ int   g_is64;

// ---------------- edge index normalization ----------------------------------
// JAX may have stored edges as int64 or int32. Node ids < 25000, so int64
// little-endian data has zero high words at every odd int32 position.
__global__ void detect_kernel(const int* __restrict__ edges_raw, int n32) {
    if (threadIdx.x == 0 && blockIdx.x == 0) {
        int nz = 0;
        int lim = n32 < 256 ? n32 : 256;
        for (int i = 1; i < lim; i += 2) nz += (edges_raw[i] != 0);
        g_is64 = (nz == 0) ? 1 : 0;
    }
}

__global__ void convert_kernel(const void* __restrict__ edges_raw, int E) {
    int e = blockIdx.x * blockDim.x + threadIdx.x;
    if (e >= E) return;
    if (g_is64) {
        const long long* p = (const long long*)edges_raw;
        g_src[e] = (int)p[e];
        g_dst[e] = (int)p[E + e];
    } else {
        const int* p = (const int*)edges_raw;
        g_src[e] = p[e];
        g_dst[e] = p[E + e];
    }
}

// ---------------- per-node precompute ----------------------------------------
// thread (n,k): pre_i[n][k], pre_j[n][k]; threads k<C_OUT also write lin part
// out[n][k] = x@W1 + b1; threads k<C_IN stash relu'd input into xr.
template <int C_IN, int C_OUT, bool RELU>
__global__ void node_kernel(const float* __restrict__ xin,
                            const float* __restrict__ W1, const float* __restrict__ b1,
                            const float* __restrict__ Wm1, const float* __restrict__ bm1,
                            float* __restrict__ xr,
                            float* __restrict__ pi, float* __restrict__ pj,
                            float* __restrict__ outbuf) {
    int idx = blockIdx.x * blockDim.x + threadIdx.x;
    if (idx >= NNODES * CMSG) return;
    int n = idx / CMSG;
    int k = idx - n * CMSG;

    float xv[C_IN];
#pragma unroll
    for (int c = 0; c < C_IN; c++) {
        float v = xin[n * C_IN + c];
        if (RELU) v = fmaxf(v, 0.f);
        xv[c] = v;
    }
    if (k < C_IN) xr[n * C_IN + k] = xv[k];

    float si = bm1[k];
    float sj = 0.f;
#pragma unroll
    for (int c = 0; c < C_IN; c++) {
        si = fmaf(xv[c], Wm1[c * CMSG + k], si);
        sj = fmaf(xv[c], Wm1[(C_IN + c) * CMSG + k], sj);
    }
    pi[n * CMSG + k] = si;
    pj[n * CMSG + k] = sj;

    if (k < C_OUT) {
        float o = b1[k];
#pragma unroll
        for (int c = 0; c < C_IN; c++) o = fmaf(xv[c], W1[c * C_OUT + k], o);
        outbuf[n * C_OUT + k] = o;
    }
}

// ---------------- per-edge kernel ---------------------------------------------
// h_k = relu(pre_i[dst][k] + pre_j[src][k])
// gate[c] = bm2[c] + sum_k h_k * Wm2[k][c]
// msg[co] = b2[co] + sum_c gate[c]*(x_i[c]-x_j[c]) * W2[c][co]
// out[dst] += msg  (vector global reductions)
template <int C_IN, int C_OUT>
__global__ void edge_kernel(int E,
                            const float* __restrict__ xr,
                            const float* __restrict__ pi, const float* __restrict__ pj,
                            const float* __restrict__ Wm2, const float* __restrict__ bm2,
                            const float* __restrict__ W2, const float* __restrict__ b2,
                            float* __restrict__ out) {
    __shared__ float sWm2[CMSG * C_IN];
    __shared__ float sW2[C_IN * C_OUT];
    __shared__ float sbm2[C_IN];
    __shared__ float sb2[C_OUT];
    for (int i = threadIdx.x; i < CMSG * C_IN; i += blockDim.x) sWm2[i] = Wm2[i];
    for (int i = threadIdx.x; i < C_IN * C_OUT; i += blockDim.x) sW2[i] = W2[i];
    if (threadIdx.x < C_IN) sbm2[threadIdx.x] = bm2[threadIdx.x];
    if (threadIdx.x < C_OUT) sb2[threadIdx.x] = b2[threadIdx.x];
    __syncthreads();

    int e = blockIdx.x * blockDim.x + threadIdx.x;
    if (e >= E) return;
    int s = g_src[e];
    int t = g_dst[e];

    float gate[C_IN];
#pragma unroll
    for (int c = 0; c < C_IN; c++) gate[c] = sbm2[c];

    const float4* a4 = reinterpret_cast<const float4*>(pi) + t * (CMSG / 4);
    const float4* b4 = reinterpret_cast<const float4*>(pj) + s * (CMSG / 4);

#pragma unroll 2
    for (int k4 = 0; k4 < CMSG / 4; k4++) {
        float4 a = a4[k4];
        float4 b = b4[k4];
        float h0 = fmaxf(a.x + b.x, 0.f);
        float h1 = fmaxf(a.y + b.y, 0.f);
        float h2 = fmaxf(a.z + b.z, 0.f);
        float h3 = fmaxf(a.w + b.w, 0.f);
        const float* w = &sWm2[(k4 * 4) * C_IN];
#pragma unroll
        for (int c = 0; c < C_IN; c++) gate[c] = fmaf(h0, w[c], gate[c]);
#pragma unroll
        for (int c = 0; c < C_IN; c++) gate[c] = fmaf(h1, w[C_IN + c], gate[c]);
#pragma unroll
        for (int c = 0; c < C_IN; c++) gate[c] = fmaf(h2, w[2 * C_IN + c], gate[c]);
#pragma unroll
        for (int c = 0; c < C_IN; c++) gate[c] = fmaf(h3, w[3 * C_IN + c], gate[c]);
    }

    const float* xt = xr + t * C_IN;
    const float* xs = xr + s * C_IN;
    float m[C_IN];
#pragma unroll
    for (int c = 0; c < C_IN; c++) m[c] = gate[c] * (xt[c] - xs[c]);

    float o[C_OUT];
#pragma unroll
    for (int co = 0; co < C_OUT; co++) o[co] = sb2[co];
#pragma unroll
    for (int c = 0; c < C_IN; c++) {
#pragma unroll
        for (int co = 0; co < C_OUT; co++) o[co] = fmaf(m[c], sW2[c * C_OUT + co], o[co]);
    }

    float* op = out + t * C_OUT;
    if constexpr (C_OUT % 4 == 0) {
#pragma unroll
        for (int co = 0; co < C_OUT; co += 4) {
            asm volatile("red.global.add.v4.f32 [%0], {%1, %2, %3, %4};"
                         :: "l"(op + co), "f"(o[co]), "f"(o[co + 1]),
                            "f"(o[co + 2]), "f"(o[co + 3])
                         : "memory");
        }
    } else {
#pragma unroll
        for (int co = 0; co < C_OUT; co++) atomicAdd(op + co, o[co]);
    }
}

// ---------------- launcher ----------------------------------------------------
extern "C" void kernel_launch(void* const* d_in, const int* in_sizes, int n_in,
                              void* d_out, int out_size) {
    const float* feat  = (const float*)d_in[0];
    const void*  edges = d_in[1];
    int E = in_sizes[1] / 2;
    if (E > EMAX) E = EMAX;

    const float* prm[27];
    for (int i = 0; i < 27; i++) prm[i] = (const float*)d_in[i];
    // per-layer param base: d=3, h=11, o=19; order W1,b1,Wm1,bm1,Wm2,bm2,W2,b2

    float *xr, *pi, *pj, *bufA, *bufB;
    cudaGetSymbolAddress((void**)&xr, g_xr);
    cudaGetSymbolAddress((void**)&pi, g_pi);
    cudaGetSymbolAddress((void**)&pj, g_pj);
    cudaGetSymbolAddress((void**)&bufA, g_bufA);
    cudaGetSymbolAddress((void**)&bufB, g_bufB);
    float* outf = (float*)d_out;

    const int TB = 256;
    int gn = (NNODES * CMSG + TB - 1) / TB;
    int ge = (E + TB - 1) / TB;

    detect_kernel<<<1, 32>>>((const int*)edges, 2 * E);
    convert_kernel<<<ge, TB>>>(edges, E);

    // layer d: 1 -> 20 (input not relu'd)
    node_kernel<1, 20, false><<<gn, TB>>>(feat, prm[3], prm[4], prm[5], prm[6],
                                          xr, pi, pj, bufA);
    edge_kernel<1, 20><<<ge, TB>>>(E, xr, pi, pj, prm[7], prm[8], prm[9], prm[10], bufA);

    // 3x layer h: 20 -> 20 (relu applied to input)
    node_kernel<20, 20, true><<<gn, TB>>>(bufA, prm[11], prm[12], prm[13], prm[14],
                                          xr, pi, pj, bufB);
    edge_kernel<20, 20><<<ge, TB>>>(E, xr, pi, pj, prm[15], prm[16], prm[17], prm[18], bufB);

    node_kernel<20, 20, true><<<gn, TB>>>(bufB, prm[11], prm[12], prm[13], prm[14],
                                          xr, pi, pj, bufA);
    edge_kernel<20, 20><<<ge, TB>>>(E, xr, pi, pj, prm[15], prm[16], prm[17], prm[18], bufA);

    node_kernel<20, 20, true><<<gn, TB>>>(bufA, prm[11], prm[12], prm[13], prm[14],
                                          xr, pi, pj, bufB);
    edge_kernel<20, 20><<<ge, TB>>>(E, xr, pi, pj, prm[15], prm[16], prm[17], prm[18], bufB);

    // layer o: 20 -> 1 (writes final output, no trailing relu)
    node_kernel<20, 1, true><<<gn, TB>>>(bufB, prm[19], prm[20], prm[21], prm[22],
                                         xr, pi, pj, outf);
    edge_kernel<20, 1><<<ge, TB>>>(E, xr, pi, pj, prm[23], prm[24], prm[25], prm[26], outf);
}

// round 5
// speedup vs baseline: 1.0367x; 1.0367x over previous
#include <cuda_runtime.h>

#define NNODES 25000
#define CMSG   200
#define EMAX   400000

// ---------------- scratch (no allocation allowed -> device globals) ----------
static __device__ float g_xr[NNODES * 20];        // relu'd layer input (for x_i - x_j)
static __device__ float g_pi[NNODES * CMSG];      // pre_i = x@Wm1_top + bm1
static __device__ float g_pj[NNODES * CMSG];      // pre_j = x@Wm1_bot
static __device__ float g_bufA[NNODES * 20];
static __device__ float g_bufB[NNODES * 20];
static __device__ int   g_src[EMAX];
static __device__ int   g_dst[EMAX];
static __device__ int   g_is64;

// ---------------- edge index normalization ----------------------------------
__global__ void detect_kernel(const int* __restrict__ edges_raw, int n32) {
    if (threadIdx.x == 0 && blockIdx.x == 0) {
        int nz = 0;
        int lim = n32 < 256 ? n32 : 256;
        for (int i = 1; i < lim; i += 2) nz += (edges_raw[i] != 0);
        g_is64 = (nz == 0) ? 1 : 0;
    }
}

__global__ void convert_kernel(const void* __restrict__ edges_raw, int E) {
    int e = blockIdx.x * blockDim.x + threadIdx.x;
    if (e >= E) return;
    if (g_is64) {
        const long long* p = (const long long*)edges_raw;
        g_src[e] = (int)p[e];
        g_dst[e] = (int)p[E + e];
    } else {
        const int* p = (const int*)edges_raw;
        g_src[e] = p[e];
        g_dst[e] = p[E + e];
    }
}

// ---------------- per-node precompute (vectorized, one float4 group/thread) --
// Output index space per node: groups [0,50) -> pre_i float4, [50,100) -> pre_j
// float4, [100, 100+GL) -> lin output group. Group 0 also stashes relu'd x.
template <int C_IN, int C_OUT, bool RELU>
__global__ void node_kernel(const float* __restrict__ xin,
                            const float* __restrict__ W1, const float* __restrict__ b1,
                            const float* __restrict__ Wm1, const float* __restrict__ bm1,
                            float* __restrict__ xr,
                            float4* __restrict__ pi4, float4* __restrict__ pj4,
                            float* __restrict__ outbuf) {
    constexpr int K4   = CMSG / 4;            // 50
    constexpr int GL   = (C_OUT + 3) / 4;
    constexpr int TOTG = 2 * K4 + GL;
    int idx = blockIdx.x * blockDim.x + threadIdx.x;
    if (idx >= NNODES * TOTG) return;
    int n = idx / TOTG;
    int g = idx - n * TOTG;

    float xv[C_IN];
#pragma unroll
    for (int c = 0; c < C_IN; c++) {
        float v = __ldg(xin + (long)n * C_IN + c);
        if (RELU) v = fmaxf(v, 0.f);
        xv[c] = v;
    }
    if (g == 0) {
#pragma unroll
        for (int c = 0; c < C_IN; c++) xr[(long)n * C_IN + c] = xv[c];
    }

    if (g < 2 * K4) {
        int half = (g >= K4) ? 1 : 0;
        int k4 = g - half * K4;
        const float4* W4 = reinterpret_cast<const float4*>(Wm1);  // [2*C_IN][K4]
        float4 acc;
        if (half) acc = make_float4(0.f, 0.f, 0.f, 0.f);
        else      acc = __ldg(reinterpret_cast<const float4*>(bm1) + k4);
#pragma unroll
        for (int c = 0; c < C_IN; c++) {
            float4 w = __ldg(W4 + (half * C_IN + c) * K4 + k4);
            acc.x = fmaf(xv[c], w.x, acc.x);
            acc.y = fmaf(xv[c], w.y, acc.y);
            acc.z = fmaf(xv[c], w.z, acc.z);
            acc.w = fmaf(xv[c], w.w, acc.w);
        }
        float4* dst = half ? pj4 : pi4;
        dst[(long)n * K4 + k4] = acc;
    } else {
        int gl = g - 2 * K4;
        if constexpr (C_OUT % 4 == 0) {
            float4 acc = __ldg(reinterpret_cast<const float4*>(b1) + gl);
#pragma unroll
            for (int c = 0; c < C_IN; c++) {
                float4 w = __ldg(reinterpret_cast<const float4*>(W1) + c * (C_OUT / 4) + gl);
                acc.x = fmaf(xv[c], w.x, acc.x);
                acc.y = fmaf(xv[c], w.y, acc.y);
                acc.z = fmaf(xv[c], w.z, acc.z);
                acc.w = fmaf(xv[c], w.w, acc.w);
            }
            reinterpret_cast<float4*>(outbuf)[(long)n * (C_OUT / 4) + gl] = acc;
        } else {
#pragma unroll
            for (int k = gl * 4; k < C_OUT && k < gl * 4 + 4; k++) {
                float o = __ldg(b1 + k);
#pragma unroll
                for (int c = 0; c < C_IN; c++)
                    o = fmaf(xv[c], __ldg(W1 + c * C_OUT + k), o);
                outbuf[(long)n * C_OUT + k] = o;
            }
        }
    }
}

// ---------------- per-edge kernel: 4 edges per thread -------------------------
// h_k = relu(pre_i[dst][k] + pre_j[src][k]); gate = h @ Wm2 + bm2;
// msg = (gate * (x_i - x_j)) @ W2 + b2; out[dst] += msg.
// Wm2 is transposed into shared as [c][k] so 4 k-values = one broadcast LDS.128
// shared by 4 edges -> 16x fewer LDS instructions, 4x fewer shared bytes.
template <int C_IN, int C_OUT>
__global__ void __launch_bounds__(128)
edge_kernel(int E,
            const float* __restrict__ xr,
            const float4* __restrict__ pi4, const float4* __restrict__ pj4,
            const float* __restrict__ Wm2, const float* __restrict__ bm2,
            const float* __restrict__ W2, const float* __restrict__ b2,
            float* __restrict__ out) {
    constexpr int K4 = CMSG / 4;  // 50
    __shared__ float sWt[C_IN * CMSG];      // transposed Wm2: [c][k]
    __shared__ float sW2s[C_IN * C_OUT];
    __shared__ float sbm2[C_IN];
    __shared__ float sb2[C_OUT];
    for (int i = threadIdx.x; i < CMSG * C_IN; i += blockDim.x) {
        int k = i / C_IN, c = i - k * C_IN;
        sWt[c * CMSG + k] = Wm2[i];
    }
    for (int i = threadIdx.x; i < C_IN * C_OUT; i += blockDim.x) sW2s[i] = W2[i];
    if (threadIdx.x < C_IN) sbm2[threadIdx.x] = bm2[threadIdx.x];
    if (threadIdx.x < C_OUT) sb2[threadIdx.x] = b2[threadIdx.x];
    __syncthreads();
    const float4* sWt4 = reinterpret_cast<const float4*>(sWt);

    int base = (blockIdx.x * blockDim.x + threadIdx.x) * 4;
    if (base >= E) return;

    int s[4], t[4];
    bool act[4];
#pragma unroll
    for (int j = 0; j < 4; j++) {
        int e = base + j;
        act[j] = (e < E);
        if (!act[j]) e = E - 1;
        s[j] = g_src[e];
        t[j] = g_dst[e];
    }

    float gate[4][C_IN];
#pragma unroll
    for (int j = 0; j < 4; j++)
#pragma unroll
        for (int c = 0; c < C_IN; c++) gate[j][c] = sbm2[c];

    long ao[4], bo[4];
#pragma unroll
    for (int j = 0; j < 4; j++) {
        ao[j] = (long)t[j] * K4;
        bo[j] = (long)s[j] * K4;
    }

#pragma unroll 1
    for (int k4 = 0; k4 < K4; k4++) {
        float4 h[4];
#pragma unroll
        for (int j = 0; j < 4; j++) {
            float4 a = __ldg(pi4 + ao[j] + k4);
            float4 b = __ldg(pj4 + bo[j] + k4);
            h[j].x = fmaxf(a.x + b.x, 0.f);
            h[j].y = fmaxf(a.y + b.y, 0.f);
            h[j].z = fmaxf(a.z + b.z, 0.f);
            h[j].w = fmaxf(a.w + b.w, 0.f);
        }
#pragma unroll
        for (int c = 0; c < C_IN; c++) {
            float4 w = sWt4[c * K4 + k4];
#pragma unroll
            for (int j = 0; j < 4; j++) {
                gate[j][c] = fmaf(h[j].x, w.x, gate[j][c]);
                gate[j][c] = fmaf(h[j].y, w.y, gate[j][c]);
                gate[j][c] = fmaf(h[j].z, w.z, gate[j][c]);
                gate[j][c] = fmaf(h[j].w, w.w, gate[j][c]);
            }
        }
    }

#pragma unroll
    for (int j = 0; j < 4; j++) {
        const float* xt = xr + (long)t[j] * C_IN;
        const float* xs = xr + (long)s[j] * C_IN;
        float o[C_OUT];
#pragma unroll
        for (int co = 0; co < C_OUT; co++) o[co] = sb2[co];
#pragma unroll
        for (int c = 0; c < C_IN; c++) {
            float m = gate[j][c] * (__ldg(xt + c) - __ldg(xs + c));
#pragma unroll
            for (int co = 0; co < C_OUT; co++)
                o[co] = fmaf(m, sW2s[c * C_OUT + co], o[co]);
        }
        if (act[j]) {
            float* op = out + (long)t[j] * C_OUT;
            if constexpr (C_OUT % 4 == 0) {
#pragma unroll
                for (int co = 0; co < C_OUT; co += 4) {
                    asm volatile("red.global.add.v4.f32 [%0], {%1, %2, %3, %4};"
                                 :: "l"(op + co), "f"(o[co]), "f"(o[co + 1]),
                                    "f"(o[co + 2]), "f"(o[co + 3])
                                 : "memory");
                }
            } else {
#pragma unroll
                for (int co = 0; co < C_OUT; co++) atomicAdd(op + co, o[co]);
            }
        }
    }
}

// ---------------- launcher ----------------------------------------------------
extern "C" void kernel_launch(void* const* d_in, const int* in_sizes, int n_in,
                              void* d_out, int out_size) {
    const float* feat  = (const float*)d_in[0];
    const void*  edges = d_in[1];
    int E = in_sizes[1] / 2;
    if (E > EMAX) E = EMAX;

    const float* prm[27];
    for (int i = 0; i < 27; i++) prm[i] = (const float*)d_in[i];
    // per-layer param base: d=3, h=11, o=19; order W1,b1,Wm1,bm1,Wm2,bm2,W2,b2

    float *xr, *pi, *pj, *bufA, *bufB;
    cudaGetSymbolAddress((void**)&xr, g_xr);
    cudaGetSymbolAddress((void**)&pi, g_pi);
    cudaGetSymbolAddress((void**)&pj, g_pj);
    cudaGetSymbolAddress((void**)&bufA, g_bufA);
    cudaGetSymbolAddress((void**)&bufB, g_bufB);
    float4* pi4 = (float4*)pi;
    float4* pj4 = (float4*)pj;
    float* outf = (float*)d_out;

    const int TBN = 256;
    const int TBE = 128;
    // node grids: TOTG = 100 + ceil(C_OUT/4)
    int gn20 = (NNODES * 105 + TBN - 1) / TBN;   // C_OUT = 20
    int gn1  = (NNODES * 101 + TBN - 1) / TBN;   // C_OUT = 1
    int geC  = (E + TBN - 1) / TBN;              // convert kernel
    int ge   = (E + 4 * TBE - 1) / (4 * TBE);    // edge kernel (4 edges/thread)

    detect_kernel<<<1, 32>>>((const int*)edges, 2 * E);
    convert_kernel<<<geC, TBN>>>(edges, E);

    // layer d: 1 -> 20 (input not relu'd)
    node_kernel<1, 20, false><<<gn20, TBN>>>(feat, prm[3], prm[4], prm[5], prm[6],
                                             xr, pi4, pj4, bufA);
    edge_kernel<1, 20><<<ge, TBE>>>(E, xr, pi4, pj4, prm[7], prm[8], prm[9], prm[10], bufA);

    // 3x layer h: 20 -> 20 (relu applied to input)
    node_kernel<20, 20, true><<<gn20, TBN>>>(bufA, prm[11], prm[12], prm[13], prm[14],
                                             xr, pi4, pj4, bufB);
    edge_kernel<20, 20><<<ge, TBE>>>(E, xr, pi4, pj4, prm[15], prm[16], prm[17], prm[18], bufB);

    node_kernel<20, 20, true><<<gn20, TBN>>>(bufB, prm[11], prm[12], prm[13], prm[14],
                                             xr, pi4, pj4, bufA);
    edge_kernel<20, 20><<<ge, TBE>>>(E, xr, pi4, pj4, prm[15], prm[16], prm[17], prm[18], bufA);

    node_kernel<20, 20, true><<<gn20, TBN>>>(bufA, prm[11], prm[12], prm[13], prm[14],
                                             xr, pi4, pj4, bufB);
    edge_kernel<20, 20><<<ge, TBE>>>(E, xr, pi4, pj4, prm[15], prm[16], prm[17], prm[18], bufB);

    // layer o: 20 -> 1 (writes final output base, then edge kernel REDs on top)
    node_kernel<20, 1, true><<<gn1, TBN>>>(bufB, prm[19], prm[20], prm[21], prm[22],
                                           xr, pi4, pj4, outf);
    edge_kernel<20, 1><<<ge, TBE>>>(E, xr, pi4, pj4, prm[23], prm[24], prm[25], prm[26], outf);
}

// round 6
// speedup vs baseline: 1.1647x; 1.1235x over previous
#include <cuda_runtime.h>

typedef unsigned long long u64;

#define NNODES 25000
#define CMSG   200
#define EMAX   400000

// ---------------- scratch (no allocation allowed -> device globals) ----------
static __device__ float g_xr[NNODES * 20];
static __device__ float g_pi[NNODES * CMSG];
static __device__ float g_pj[NNODES * CMSG];
static __device__ float g_bufA[NNODES * 20];
static __device__ float g_bufB[NNODES * 20];
static __device__ int   g_src[EMAX];
static __device__ int   g_dst[EMAX];
static __device__ int   g_is64;

// ---------------- packed fp32x2 helpers (Blackwell FFMA2) --------------------
__device__ __forceinline__ u64 pack2(float lo, float hi) {
    u64 r; asm("mov.b64 %0, {%1, %2};" : "=l"(r) : "f"(lo), "f"(hi)); return r;
}
__device__ __forceinline__ u64 packbb(float v) { return pack2(v, v); }
__device__ __forceinline__ void fma2(u64& d, u64 a, u64 b) {
    asm("fma.rn.f32x2 %0, %1, %2, %0;" : "+l"(d) : "l"(a), "l"(b));
}
__device__ __forceinline__ float2 un2(u64 v) {
    float2 f; asm("mov.b64 {%0, %1}, %2;" : "=f"(f.x), "=f"(f.y) : "l"(v)); return f;
}

// ---------------- edge index normalization ----------------------------------
__global__ void detect_kernel(const int* __restrict__ edges_raw, int n32) {
    if (threadIdx.x == 0 && blockIdx.x == 0) {
        int nz = 0;
        int lim = n32 < 256 ? n32 : 256;
        for (int i = 1; i < lim; i += 2) nz += (edges_raw[i] != 0);
        g_is64 = (nz == 0) ? 1 : 0;
    }
}

__global__ void convert_kernel(const void* __restrict__ edges_raw, int E) {
    int e = blockIdx.x * blockDim.x + threadIdx.x;
    if (e >= E) return;
    if (g_is64) {
        const long long* p = (const long long*)edges_raw;
        g_src[e] = (int)p[e];
        g_dst[e] = (int)p[E + e];
    } else {
        const int* p = (const int*)edges_raw;
        g_src[e] = p[e];
        g_dst[e] = p[E + e];
    }
}

// ---------------- d-layer node kernel (C_IN = 1): lin + xr only --------------
__global__ void node_d_kernel(const float* __restrict__ feat,
                              const float* __restrict__ W1, const float* __restrict__ b1,
                              float* __restrict__ xr, float* __restrict__ out) {
    int n = blockIdx.x * blockDim.x + threadIdx.x;
    if (n >= NNODES) return;
    float x = __ldg(feat + n);
    xr[n] = x;
    float4* o4 = reinterpret_cast<float4*>(out + n * 20);
    const float4* w4 = reinterpret_cast<const float4*>(W1);
    const float4* b4 = reinterpret_cast<const float4*>(b1);
#pragma unroll
    for (int g = 0; g < 5; g++) {
        float4 w = __ldg(w4 + g);
        float4 b = __ldg(b4 + g);
        o4[g] = make_float4(fmaf(x, w.x, b.x), fmaf(x, w.y, b.y),
                            fmaf(x, w.z, b.z), fmaf(x, w.w, b.w));
    }
}

// ---------------- generic node precompute (C_IN = 20) ------------------------
template <int C_IN, int C_OUT, bool RELU>
__global__ void node_kernel(const float* __restrict__ xin,
                            const float* __restrict__ W1, const float* __restrict__ b1,
                            const float* __restrict__ Wm1, const float* __restrict__ bm1,
                            float* __restrict__ xr,
                            float4* __restrict__ pi4, float4* __restrict__ pj4,
                            float* __restrict__ outbuf) {
    constexpr int K4   = CMSG / 4;            // 50
    constexpr int GL   = (C_OUT + 3) / 4;
    constexpr int TOTG = 2 * K4 + GL;
    int idx = blockIdx.x * blockDim.x + threadIdx.x;
    if (idx >= NNODES * TOTG) return;
    int n = idx / TOTG;
    int g = idx - n * TOTG;

    float xv[C_IN];
#pragma unroll
    for (int c = 0; c < C_IN; c++) {
        float v = __ldg(xin + (long)n * C_IN + c);
        if (RELU) v = fmaxf(v, 0.f);
        xv[c] = v;
    }
    if (g == 0) {
#pragma unroll
        for (int c = 0; c < C_IN; c++) xr[(long)n * C_IN + c] = xv[c];
    }

    if (g < 2 * K4) {
        int half = (g >= K4) ? 1 : 0;
        int k4 = g - half * K4;
        const float4* W4 = reinterpret_cast<const float4*>(Wm1);  // [2*C_IN][K4]
        float4 acc;
        if (half) acc = make_float4(0.f, 0.f, 0.f, 0.f);
        else      acc = __ldg(reinterpret_cast<const float4*>(bm1) + k4);
#pragma unroll
        for (int c = 0; c < C_IN; c++) {
            float4 w = __ldg(W4 + (half * C_IN + c) * K4 + k4);
            acc.x = fmaf(xv[c], w.x, acc.x);
            acc.y = fmaf(xv[c], w.y, acc.y);
            acc.z = fmaf(xv[c], w.z, acc.z);
            acc.w = fmaf(xv[c], w.w, acc.w);
        }
        float4* dst = half ? pj4 : pi4;
        dst[(long)n * K4 + k4] = acc;
    } else {
        int gl = g - 2 * K4;
        if constexpr (C_OUT % 4 == 0) {
            float4 acc = __ldg(reinterpret_cast<const float4*>(b1) + gl);
#pragma unroll
            for (int c = 0; c < C_IN; c++) {
                float4 w = __ldg(reinterpret_cast<const float4*>(W1) + c * (C_OUT / 4) + gl);
                acc.x = fmaf(xv[c], w.x, acc.x);
                acc.y = fmaf(xv[c], w.y, acc.y);
                acc.z = fmaf(xv[c], w.z, acc.z);
                acc.w = fmaf(xv[c], w.w, acc.w);
            }
            reinterpret_cast<float4*>(outbuf)[(long)n * (C_OUT / 4) + gl] = acc;
        } else {
#pragma unroll
            for (int k = gl * 4; k < C_OUT && k < gl * 4 + 4; k++) {
                float o = __ldg(b1 + k);
#pragma unroll
                for (int c = 0; c < C_IN; c++)
                    o = fmaf(xv[c], __ldg(W1 + c * C_OUT + k), o);
                outbuf[(long)n * C_OUT + k] = o;
            }
        }
    }
}

// ---------------- d-layer edge kernel (C_IN = 1): h computed on the fly ------
// h_k = relu(xi*A[k] + xj*B[k] + bm1[k]); gate = h . Wm2 + bm2 (scalar);
// msg[co] = gate*(xi-xj)*W2[co] + b2[co]; out[dst] += msg.
// Gathers only 8 B/edge instead of 1600 B/edge.
__global__ void __launch_bounds__(256)
edge_d_kernel(int E, const float* __restrict__ xr,
              const float* __restrict__ Wm1, const float* __restrict__ bm1,
              const float* __restrict__ Wm2, const float* __restrict__ bm2,
              const float* __restrict__ W2, const float* __restrict__ b2,
              float* __restrict__ out) {
    __shared__ float4 sA[50], sB[50], sbm[50], sw[50];
    __shared__ float sW2v[20], sb2v[20];
    __shared__ float sbm2;
    int tid = threadIdx.x;
    if (tid < 50) {
        sA[tid]  = __ldg(reinterpret_cast<const float4*>(Wm1) + tid);
        sB[tid]  = __ldg(reinterpret_cast<const float4*>(Wm1 + CMSG) + tid);
        sbm[tid] = __ldg(reinterpret_cast<const float4*>(bm1) + tid);
        sw[tid]  = __ldg(reinterpret_cast<const float4*>(Wm2) + tid);
    }
    if (tid < 20) { sW2v[tid] = W2[tid]; sb2v[tid] = b2[tid]; }
    if (tid == 0) sbm2 = bm2[0];
    __syncthreads();

    int e = blockIdx.x * blockDim.x + tid;
    if (e >= E) return;
    int s = g_src[e], t = g_dst[e];
    float xi = __ldg(xr + t);
    float xj = __ldg(xr + s);

    float gate = sbm2;
#pragma unroll 2
    for (int k = 0; k < 50; k++) {
        float4 A = sA[k], B = sB[k], bm = sbm[k], w = sw[k];
        float h0 = fmaxf(fmaf(xi, A.x, fmaf(xj, B.x, bm.x)), 0.f);
        float h1 = fmaxf(fmaf(xi, A.y, fmaf(xj, B.y, bm.y)), 0.f);
        float h2 = fmaxf(fmaf(xi, A.z, fmaf(xj, B.z, bm.z)), 0.f);
        float h3 = fmaxf(fmaf(xi, A.w, fmaf(xj, B.w, bm.w)), 0.f);
        gate = fmaf(h0, w.x, gate);
        gate = fmaf(h1, w.y, gate);
        gate = fmaf(h2, w.z, gate);
        gate = fmaf(h3, w.w, gate);
    }

    float m = gate * (xi - xj);
    float* op = out + (long)t * 20;
#pragma unroll
    for (int co = 0; co < 20; co += 4) {
        float o0 = fmaf(m, sW2v[co],     sb2v[co]);
        float o1 = fmaf(m, sW2v[co + 1], sb2v[co + 1]);
        float o2 = fmaf(m, sW2v[co + 2], sb2v[co + 2]);
        float o3 = fmaf(m, sW2v[co + 3], sb2v[co + 3]);
        asm volatile("red.global.add.v4.f32 [%0], {%1, %2, %3, %4};"
                     :: "l"(op + co), "f"(o0), "f"(o1), "f"(o2), "f"(o3) : "memory");
    }
}

// ---------------- generic edge kernel (C_IN even): packed fp32x2 GEMMs -------
template <int C_IN, int C_OUT>
__global__ void __launch_bounds__(256)
edge_kernel(int E,
            const float* __restrict__ xr,
            const float4* __restrict__ pi4, const float4* __restrict__ pj4,
            const float* __restrict__ Wm2, const float* __restrict__ bm2,
            const float* __restrict__ W2, const float* __restrict__ b2,
            float* __restrict__ out) {
    static_assert(C_IN % 4 == 0, "C_IN must be multiple of 4");
    constexpr int K4 = CMSG / 4;      // 50
    constexpr int CP = C_IN / 2;      // c-pairs (10)
    __shared__ float sWm2[CMSG * C_IN];   // row-major [k][c]; pairs contiguous
    __shared__ float sW2s[C_IN * C_OUT];  // row-major [c][co]
    __shared__ float sbm2[C_IN];
    __shared__ float sb2[C_OUT];
    {
        const float4* src = reinterpret_cast<const float4*>(Wm2);
        float4* dst = reinterpret_cast<float4*>(sWm2);
        for (int i = threadIdx.x; i < CMSG * C_IN / 4; i += blockDim.x)
            dst[i] = __ldg(src + i);
        for (int i = threadIdx.x; i < C_IN * C_OUT; i += blockDim.x)
            sW2s[i] = W2[i];
        if (threadIdx.x < C_IN) sbm2[threadIdx.x] = bm2[threadIdx.x];
        if (threadIdx.x < C_OUT) sb2[threadIdx.x] = b2[threadIdx.x];
    }
    __syncthreads();

    int e = blockIdx.x * blockDim.x + threadIdx.x;
    if (e >= E) return;
    int s = g_src[e], t = g_dst[e];

    u64 gate2[CP];
#pragma unroll
    for (int cp = 0; cp < CP; cp++) gate2[cp] = pack2(sbm2[2 * cp], sbm2[2 * cp + 1]);

    const float4* pa = pi4 + (long)t * K4;
    const float4* pb = pj4 + (long)s * K4;

#pragma unroll 2
    for (int k4 = 0; k4 < K4; k4++) {
        float4 a = __ldg(pa + k4);
        float4 b = __ldg(pb + k4);
        float h0 = fmaxf(a.x + b.x, 0.f);
        float h1 = fmaxf(a.y + b.y, 0.f);
        float h2 = fmaxf(a.z + b.z, 0.f);
        float h3 = fmaxf(a.w + b.w, 0.f);
        const float* wrow = sWm2 + (k4 * 4) * C_IN;
        u64 hb;
        // h0
        hb = packbb(h0);
#pragma unroll
        for (int q = 0; q < C_IN / 4; q++) {
            ulonglong2 wp = reinterpret_cast<const ulonglong2*>(wrow)[q];
            fma2(gate2[2 * q], hb, wp.x);
            fma2(gate2[2 * q + 1], hb, wp.y);
        }
        // h1
        hb = packbb(h1);
#pragma unroll
        for (int q = 0; q < C_IN / 4; q++) {
            ulonglong2 wp = reinterpret_cast<const ulonglong2*>(wrow + C_IN)[q];
            fma2(gate2[2 * q], hb, wp.x);
            fma2(gate2[2 * q + 1], hb, wp.y);
        }
        // h2
        hb = packbb(h2);
#pragma unroll
        for (int q = 0; q < C_IN / 4; q++) {
            ulonglong2 wp = reinterpret_cast<const ulonglong2*>(wrow + 2 * C_IN)[q];
            fma2(gate2[2 * q], hb, wp.x);
            fma2(gate2[2 * q + 1], hb, wp.y);
        }
        // h3
        hb = packbb(h3);
#pragma unroll
        for (int q = 0; q < C_IN / 4; q++) {
            ulonglong2 wp = reinterpret_cast<const ulonglong2*>(wrow + 3 * C_IN)[q];
            fma2(gate2[2 * q], hb, wp.x);
            fma2(gate2[2 * q + 1], hb, wp.y);
        }
    }

    // m[c] = gate[c] * (x_i[c] - x_j[c])
    float m[C_IN];
    {
        const float4* xt4 = reinterpret_cast<const float4*>(xr + (long)t * C_IN);
        const float4* xs4 = reinterpret_cast<const float4*>(xr + (long)s * C_IN);
#pragma unroll
        for (int g = 0; g < C_IN / 4; g++) {
            float4 xt = __ldg(xt4 + g);
            float4 xs = __ldg(xs4 + g);
            float2 g0 = un2(gate2[2 * g]);
            float2 g1 = un2(gate2[2 * g + 1]);
            m[4 * g + 0] = g0.x * (xt.x - xs.x);
            m[4 * g + 1] = g0.y * (xt.y - xs.y);
            m[4 * g + 2] = g1.x * (xt.z - xs.z);
            m[4 * g + 3] = g1.y * (xt.w - xs.w);
        }
    }

    if constexpr (C_OUT % 4 == 0) {
        u64 o2[C_OUT / 2];
#pragma unroll
        for (int p = 0; p < C_OUT / 2; p++) o2[p] = pack2(sb2[2 * p], sb2[2 * p + 1]);
#pragma unroll
        for (int c = 0; c < C_IN; c++) {
            u64 mb = packbb(m[c]);
            const float* wr = sW2s + c * C_OUT;
#pragma unroll
            for (int q = 0; q < C_OUT / 4; q++) {
                ulonglong2 wp = reinterpret_cast<const ulonglong2*>(wr)[q];
                fma2(o2[2 * q], mb, wp.x);
                fma2(o2[2 * q + 1], mb, wp.y);
            }
        }
        float* op = out + (long)t * C_OUT;
#pragma unroll
        for (int q = 0; q < C_OUT / 4; q++) {
            float2 a = un2(o2[2 * q]);
            float2 b = un2(o2[2 * q + 1]);
            asm volatile("red.global.add.v4.f32 [%0], {%1, %2, %3, %4};"
                         :: "l"(op + 4 * q), "f"(a.x), "f"(a.y), "f"(b.x), "f"(b.y)
                         : "memory");
        }
    } else {
        // C_OUT == 1 (o-layer)
        float o = sb2[0];
#pragma unroll
        for (int c = 0; c < C_IN; c++) o = fmaf(m[c], sW2s[c], o);
        atomicAdd(out + t, o);
    }
}

// ---------------- launcher ----------------------------------------------------
extern "C" void kernel_launch(void* const* d_in, const int* in_sizes, int n_in,
                              void* d_out, int out_size) {
    const float* feat  = (const float*)d_in[0];
    const void*  edges = d_in[1];
    int E = in_sizes[1] / 2;
    if (E > EMAX) E = EMAX;

    const float* prm[27];
    for (int i = 0; i < 27; i++) prm[i] = (const float*)d_in[i];
    // per-layer param base: d=3, h=11, o=19; order W1,b1,Wm1,bm1,Wm2,bm2,W2,b2

    float *xr, *pi, *pj, *bufA, *bufB;
    cudaGetSymbolAddress((void**)&xr, g_xr);
    cudaGetSymbolAddress((void**)&pi, g_pi);
    cudaGetSymbolAddress((void**)&pj, g_pj);
    cudaGetSymbolAddress((void**)&bufA, g_bufA);
    cudaGetSymbolAddress((void**)&bufB, g_bufB);
    float4* pi4 = (float4*)pi;
    float4* pj4 = (float4*)pj;
    float* outf = (float*)d_out;

    const int TB = 256;
    int gn20 = (NNODES * 105 + TB - 1) / TB;   // node: C_OUT = 20
    int gn1  = (NNODES * 101 + TB - 1) / TB;   // node: C_OUT = 1
    int gnd  = (NNODES + TB - 1) / TB;         // d-layer node
    int ge   = (E + TB - 1) / TB;              // edge kernels (1 edge/thread)

    detect_kernel<<<1, 32>>>((const int*)edges, 2 * E);
    convert_kernel<<<ge, TB>>>(edges, E);

    // layer d: 1 -> 20 (no relu on input; h computed on the fly in edge kernel)
    node_d_kernel<<<gnd, TB>>>(feat, prm[3], prm[4], xr, bufA);
    edge_d_kernel<<<ge, TB>>>(E, xr, prm[5], prm[6], prm[7], prm[8], prm[9], prm[10], bufA);

    // 3x layer h: 20 -> 20 (relu applied to input)
    node_kernel<20, 20, true><<<gn20, TB>>>(bufA, prm[11], prm[12], prm[13], prm[14],
                                            xr, pi4, pj4, bufB);
    edge_kernel<20, 20><<<ge, TB>>>(E, xr, pi4, pj4, prm[15], prm[16], prm[17], prm[18], bufB);

    node_kernel<20, 20, true><<<gn20, TB>>>(bufB, prm[11], prm[12], prm[13], prm[14],
                                            xr, pi4, pj4, bufA);
    edge_kernel<20, 20><<<ge, TB>>>(E, xr, pi4, pj4, prm[15], prm[16], prm[17], prm[18], bufA);

    node_kernel<20, 20, true><<<gn20, TB>>>(bufA, prm[11], prm[12], prm[13], prm[14],
                                            xr, pi4, pj4, bufB);
    edge_kernel<20, 20><<<ge, TB>>>(E, xr, pi4, pj4, prm[15], prm[16], prm[17], prm[18], bufB);

    // layer o: 20 -> 1 (node kernel writes base into d_out, edge kernel REDs on top)
    node_kernel<20, 1, true><<<gn1, TB>>>(bufB, prm[19], prm[20], prm[21], prm[22],
                                          xr, pi4, pj4, outf);
    edge_kernel<20, 1><<<ge, TB>>>(E, xr, pi4, pj4, prm[23], prm[24], prm[25], prm[26], outf);
}

// round 7
// speedup vs baseline: 1.3573x; 1.1654x over previous
#include <cuda_runtime.h>

typedef unsigned long long u64;

#define NNODES 25000
#define CMSG   200
#define EMAX   400000

// ---------------- scratch (no allocation allowed -> device globals) ----------
static __device__ float g_xr[NNODES * 20];
static __device__ float g_pi[NNODES * CMSG];
static __device__ float g_pj[NNODES * CMSG];
static __device__ float g_bufA[NNODES * 20];
static __device__ float g_bufB[NNODES * 20];
static __device__ int   g_src[EMAX];
static __device__ int   g_dst[EMAX];
static __device__ int   g_is64;

// ---------------- packed fp32x2 helpers --------------------------------------
__device__ __forceinline__ u64 pack2(float lo, float hi) {
    u64 r; asm("mov.b64 %0, {%1, %2};" : "=l"(r) : "f"(lo), "f"(hi)); return r;
}
__device__ __forceinline__ u64 packbb(float v) { return pack2(v, v); }
__device__ __forceinline__ void fma2(u64& d, u64 a, u64 b) {
    asm("fma.rn.f32x2 %0, %1, %2, %0;" : "+l"(d) : "l"(a), "l"(b));
}
__device__ __forceinline__ void add2(u64& d, u64 a) {
    asm("add.rn.f32x2 %0, %0, %1;" : "+l"(d) : "l"(a));
}
__device__ __forceinline__ float2 un2(u64 v) {
    float2 f; asm("mov.b64 {%0, %1}, %2;" : "=f"(f.x), "=f"(f.y) : "l"(v)); return f;
}

// ---------------- edge index normalization ----------------------------------
__global__ void detect_kernel(const int* __restrict__ edges_raw, int n32) {
    if (threadIdx.x == 0 && blockIdx.x == 0) {
        int nz = 0;
        int lim = n32 < 256 ? n32 : 256;
        for (int i = 1; i < lim; i += 2) nz += (edges_raw[i] != 0);
        g_is64 = (nz == 0) ? 1 : 0;
    }
}

__global__ void convert_kernel(const void* __restrict__ edges_raw, int E) {
    int e = blockIdx.x * blockDim.x + threadIdx.x;
    if (e >= E) return;
    if (g_is64) {
        const long long* p = (const long long*)edges_raw;
        g_src[e] = (int)p[e];
        g_dst[e] = (int)p[E + e];
    } else {
        const int* p = (const int*)edges_raw;
        g_src[e] = p[e];
        g_dst[e] = p[E + e];
    }
}

// ---------------- d-layer node kernel ----------------------------------------
__global__ void node_d_kernel(const float* __restrict__ feat,
                              const float* __restrict__ W1, const float* __restrict__ b1,
                              float* __restrict__ xr, float* __restrict__ out) {
    int n = blockIdx.x * blockDim.x + threadIdx.x;
    if (n >= NNODES) return;
    float x = __ldg(feat + n);
    xr[n] = x;
    float4* o4 = reinterpret_cast<float4*>(out + n * 20);
    const float4* w4 = reinterpret_cast<const float4*>(W1);
    const float4* b4 = reinterpret_cast<const float4*>(b1);
#pragma unroll
    for (int g = 0; g < 5; g++) {
        float4 w = __ldg(w4 + g);
        float4 b = __ldg(b4 + g);
        o4[g] = make_float4(fmaf(x, w.x, b.x), fmaf(x, w.y, b.y),
                            fmaf(x, w.z, b.z), fmaf(x, w.w, b.w));
    }
}

// ---------------- generic node precompute (C_IN = 20) ------------------------
template <int C_OUT>
__global__ void node_kernel(const float* __restrict__ xin,
                            const float* __restrict__ W1, const float* __restrict__ b1,
                            const float* __restrict__ Wm1, const float* __restrict__ bm1,
                            float* __restrict__ xr,
                            float4* __restrict__ pi4, float4* __restrict__ pj4,
                            float* __restrict__ outbuf) {
    constexpr int C_IN = 20;
    constexpr int K4   = CMSG / 4;            // 50
    constexpr int GL   = (C_OUT + 3) / 4;
    constexpr int TOTG = 2 * K4 + GL;
    int idx = blockIdx.x * blockDim.x + threadIdx.x;
    if (idx >= NNODES * TOTG) return;
    int n = idx / TOTG;
    int g = idx - n * TOTG;

    float xv[C_IN];
    {
        const float4* x4 = reinterpret_cast<const float4*>(xin + (long)n * C_IN);
#pragma unroll
        for (int q = 0; q < C_IN / 4; q++) {
            float4 v = __ldg(x4 + q);
            xv[4 * q + 0] = fmaxf(v.x, 0.f);
            xv[4 * q + 1] = fmaxf(v.y, 0.f);
            xv[4 * q + 2] = fmaxf(v.z, 0.f);
            xv[4 * q + 3] = fmaxf(v.w, 0.f);
        }
    }
    if (g == 0) {
        float4* xr4 = reinterpret_cast<float4*>(xr + (long)n * C_IN);
#pragma unroll
        for (int q = 0; q < C_IN / 4; q++)
            xr4[q] = make_float4(xv[4 * q], xv[4 * q + 1], xv[4 * q + 2], xv[4 * q + 3]);
    }

    if (g < 2 * K4) {
        int half = (g >= K4) ? 1 : 0;
        int k4 = g - half * K4;
        const float4* W4 = reinterpret_cast<const float4*>(Wm1);  // [2*C_IN][K4]
        float4 acc;
        if (half) acc = make_float4(0.f, 0.f, 0.f, 0.f);
        else      acc = __ldg(reinterpret_cast<const float4*>(bm1) + k4);
#pragma unroll
        for (int c = 0; c < C_IN; c++) {
            float4 w = __ldg(W4 + (half * C_IN + c) * K4 + k4);
            acc.x = fmaf(xv[c], w.x, acc.x);
            acc.y = fmaf(xv[c], w.y, acc.y);
            acc.z = fmaf(xv[c], w.z, acc.z);
            acc.w = fmaf(xv[c], w.w, acc.w);
        }
        float4* dst = half ? pj4 : pi4;
        dst[(long)n * K4 + k4] = acc;
    } else {
        int gl = g - 2 * K4;
        if constexpr (C_OUT % 4 == 0) {
            float4 acc = __ldg(reinterpret_cast<const float4*>(b1) + gl);
#pragma unroll
            for (int c = 0; c < C_IN; c++) {
                float4 w = __ldg(reinterpret_cast<const float4*>(W1) + c * (C_OUT / 4) + gl);
                acc.x = fmaf(xv[c], w.x, acc.x);
                acc.y = fmaf(xv[c], w.y, acc.y);
                acc.z = fmaf(xv[c], w.z, acc.z);
                acc.w = fmaf(xv[c], w.w, acc.w);
            }
            reinterpret_cast<float4*>(outbuf)[(long)n * (C_OUT / 4) + gl] = acc;
        } else {
#pragma unroll
            for (int k = gl * 4; k < C_OUT && k < gl * 4 + 4; k++) {
                float o = __ldg(b1 + k);
#pragma unroll
                for (int c = 0; c < C_IN; c++)
                    o = fmaf(xv[c], __ldg(W1 + c * C_OUT + k), o);
                outbuf[(long)n * C_OUT + k] = o;
            }
        }
    }
}

// ---------------- d-layer edge kernel (C_IN = 1) ------------------------------
__global__ void __launch_bounds__(256)
edge_d_kernel(int E, const float* __restrict__ xr,
              const float* __restrict__ Wm1, const float* __restrict__ bm1,
              const float* __restrict__ Wm2, const float* __restrict__ bm2,
              const float* __restrict__ W2, const float* __restrict__ b2,
              float* __restrict__ out) {
    __shared__ float4 sA[50], sB[50], sbm[50], sw[50];
    __shared__ float sW2v[20], sb2v[20];
    __shared__ float sbm2;
    int tid = threadIdx.x;
    if (tid < 50) {
        sA[tid]  = __ldg(reinterpret_cast<const float4*>(Wm1) + tid);
        sB[tid]  = __ldg(reinterpret_cast<const float4*>(Wm1 + CMSG) + tid);
        sbm[tid] = __ldg(reinterpret_cast<const float4*>(bm1) + tid);
        sw[tid]  = __ldg(reinterpret_cast<const float4*>(Wm2) + tid);
    }
    if (tid < 20) { sW2v[tid] = W2[tid]; sb2v[tid] = b2[tid]; }
    if (tid == 0) sbm2 = bm2[0];
    __syncthreads();

    int e = blockIdx.x * blockDim.x + tid;
    if (e >= E) return;
    int s = g_src[e], t = g_dst[e];
    float xi = __ldg(xr + t);
    float xj = __ldg(xr + s);

    float gate = sbm2;
#pragma unroll 2
    for (int k = 0; k < 50; k++) {
        float4 A = sA[k], B = sB[k], bm = sbm[k], w = sw[k];
        float h0 = fmaxf(fmaf(xi, A.x, fmaf(xj, B.x, bm.x)), 0.f);
        float h1 = fmaxf(fmaf(xi, A.y, fmaf(xj, B.y, bm.y)), 0.f);
        float h2 = fmaxf(fmaf(xi, A.z, fmaf(xj, B.z, bm.z)), 0.f);
        float h3 = fmaxf(fmaf(xi, A.w, fmaf(xj, B.w, bm.w)), 0.f);
        gate = fmaf(h0, w.x, gate);
        gate = fmaf(h1, w.y, gate);
        gate = fmaf(h2, w.z, gate);
        gate = fmaf(h3, w.w, gate);
    }

    float m = gate * (xi - xj);
    float* op = out + (long)t * 20;
#pragma unroll
    for (int co = 0; co < 20; co += 4) {
        float o0 = fmaf(m, sW2v[co],     sb2v[co]);
        float o1 = fmaf(m, sW2v[co + 1], sb2v[co + 1]);
        float o2 = fmaf(m, sW2v[co + 2], sb2v[co + 2]);
        float o3 = fmaf(m, sW2v[co + 3], sb2v[co + 3]);
        asm volatile("red.global.add.v4.f32 [%0], {%1, %2, %3, %4};"
                     :: "l"(op + co), "f"(o0), "f"(o1), "f"(o2), "f"(o3) : "memory");
    }
}

// ---------------- staged edge kernel (C_IN = 20) ------------------------------
// Pass 1 (per k-chunk): 256 threads cooperatively gather pi/pj rows for 128
// edges (coalesced LDG.128) and store h = relu(pi+pj) into smem.
// Pass 2: 2 threads per edge, each owns 10 gate channels (f32x2 pairs);
// msg partials combined via shfl_xor; half 0 issues REDs.
#define TE     128
#define KCH    25   // float4 per chunk (100 floats); 2 chunks
// dynamic smem carve offsets (bytes)
#define OFF_HBUF  0
#define SZ_HBUF   (TE * KCH * 16)           // 51200
#define OFF_WM2P  (OFF_HBUF + SZ_HBUF)      // 51200
#define SZ_WM2P   (CMSG * 24 * 4)           // 19200 (rows padded 20 -> 24, gap at 10)
#define OFF_W2S   (OFF_WM2P + SZ_WM2P)      // 70400
#define SZ_W2S    (20 * 20 * 4)             // max C_OUT=20
#define OFF_BM2   (OFF_W2S + SZ_W2S)        // 72000
#define OFF_B2    (OFF_BM2 + 96)            // 72096
#define OFF_SRC   (OFF_B2 + 96)             // 72192
#define OFF_DST   (OFF_SRC + TE * 4)        // 72704
#define SMEM_TOT  (OFF_DST + TE * 4)        // 73216

template <int C_OUT>
__global__ void __launch_bounds__(256)
edge_staged_kernel(int E, int ntiles,
                   const float* __restrict__ xr,
                   const float4* __restrict__ pi4, const float4* __restrict__ pj4,
                   const float* __restrict__ Wm2, const float* __restrict__ bm2,
                   const float* __restrict__ W2, const float* __restrict__ b2,
                   float* __restrict__ out) {
    extern __shared__ char dyn[];
    float4* hbuf4 = reinterpret_cast<float4*>(dyn + OFF_HBUF);
    float*  sWm2p = reinterpret_cast<float*>(dyn + OFF_WM2P);
    float*  sW2s  = reinterpret_cast<float*>(dyn + OFF_W2S);
    float*  sbm2  = reinterpret_cast<float*>(dyn + OFF_BM2);
    float*  sb2   = reinterpret_cast<float*>(dyn + OFF_B2);
    int*    ssrc  = reinterpret_cast<int*>(dyn + OFF_SRC);
    int*    sdst  = reinterpret_cast<int*>(dyn + OFF_DST);

    int tid = threadIdx.x;
    // weights once per block
    for (int i = tid; i < CMSG * 20; i += 256) {
        int k = i / 20, c = i - k * 20;
        sWm2p[k * 24 + c + ((c >= 10) ? 2 : 0)] = Wm2[i];
    }
    for (int i = tid; i < 20 * C_OUT; i += 256) sW2s[i] = W2[i];
    if (tid < 20) sbm2[tid] = bm2[tid];
    if (tid < C_OUT) sb2[tid] = b2[tid];

    int eloc = tid >> 1;
    int half = tid & 1;
    int c0 = half * 10;

    for (int tile = blockIdx.x; tile < ntiles; tile += gridDim.x) {
        int e0 = tile * TE;
        int tileE = E - e0; if (tileE > TE) tileE = TE;

        __syncthreads();   // protect ssrc/hbuf from previous tile readers
        for (int i = tid; i < TE; i += 256) {
            int e = e0 + ((i < tileE) ? i : (tileE - 1));
            ssrc[i] = g_src[e];
            sdst[i] = g_dst[e];
        }
        __syncthreads();

        bool act = (eloc < tileE);
        int s = ssrc[eloc];
        int t = sdst[eloc];

        u64 gate2[5];
#pragma unroll
        for (int p = 0; p < 5; p++) gate2[p] = pack2(sbm2[c0 + 2 * p], sbm2[c0 + 2 * p + 1]);

#pragma unroll
        for (int ch = 0; ch < 2; ch++) {
            // ---- stage chunk: coalesced gather + relu ----
#pragma unroll 1
            for (int slot = tid; slot < TE * KCH; slot += 256) {
                int e = slot / KCH;
                int k4 = slot - e * KCH;
                if (e < tileE) {
                    int kg = ch * KCH + k4;
                    float4 a = __ldg(pi4 + (long)sdst[e] * 50 + kg);
                    float4 b = __ldg(pj4 + (long)ssrc[e] * 50 + kg);
                    float4 h;
                    h.x = fmaxf(a.x + b.x, 0.f);
                    h.y = fmaxf(a.y + b.y, 0.f);
                    h.z = fmaxf(a.z + b.z, 0.f);
                    h.w = fmaxf(a.w + b.w, 0.f);
                    hbuf4[e * KCH + k4] = h;
                }
            }
            __syncthreads();
            // ---- accumulate gates for own edge/half ----
#pragma unroll 1
            for (int k4 = 0; k4 < KCH; k4++) {
                float4 h = hbuf4[eloc * KCH + k4];
                const float* wbase = sWm2p + (ch * KCH + k4) * 4 * 24 + half * 12;
                float hs[4] = {h.x, h.y, h.z, h.w};
#pragma unroll
                for (int j = 0; j < 4; j++) {
                    u64 hb = packbb(hs[j]);
                    const ulonglong2* wr = reinterpret_cast<const ulonglong2*>(wbase + j * 24);
#pragma unroll
                    for (int p = 0; p < 5; p += 2) {   // 5 u2 per half-row? no: 5 pairs
                    }
                    // 5 ulonglong2 (10 floats = 5 f32x2 pairs)
                    ulonglong2 w0 = wr[0];
                    fma2(gate2[0], hb, w0.x);
                    fma2(gate2[1], hb, w0.y);
                    ulonglong2 w1 = wr[1];
                    fma2(gate2[2], hb, w1.x);
                    fma2(gate2[3], hb, w1.y);
                    u64 w2v = *reinterpret_cast<const u64*>(wbase + j * 24 + 8);
                    fma2(gate2[4], hb, w2v);
                }
            }
            __syncthreads();
        }

        // ---- msg + scatter ----
        float m[10];
        {
            const float2* xt2 = reinterpret_cast<const float2*>(xr + (long)t * 20 + c0);
            const float2* xs2 = reinterpret_cast<const float2*>(xr + (long)s * 20 + c0);
#pragma unroll
            for (int p = 0; p < 5; p++) {
                float2 xt = __ldg(xt2 + p);
                float2 xs = __ldg(xs2 + p);
                float2 g = un2(gate2[p]);
                m[2 * p]     = g.x * (xt.x - xs.x);
                m[2 * p + 1] = g.y * (xt.y - xs.y);
            }
        }

        if constexpr (C_OUT == 20) {
            u64 o2[10];
#pragma unroll
            for (int p = 0; p < 10; p++)
                o2[p] = half ? 0ULL : pack2(sb2[2 * p], sb2[2 * p + 1]);
#pragma unroll
            for (int cl = 0; cl < 10; cl++) {
                u64 mb = packbb(m[cl]);
                const ulonglong2* wr =
                    reinterpret_cast<const ulonglong2*>(sW2s + (c0 + cl) * 20);
#pragma unroll
                for (int q = 0; q < 5; q++) {
                    ulonglong2 w = wr[q];
                    fma2(o2[2 * q], mb, w.x);
                    fma2(o2[2 * q + 1], mb, w.y);
                }
            }
#pragma unroll
            for (int p = 0; p < 10; p++) {
                u64 other = __shfl_xor_sync(0xFFFFFFFFu, o2[p], 1);
                add2(o2[p], other);
            }
            if (act && half == 0) {
                float* op = out + (long)t * 20;
#pragma unroll
                for (int q = 0; q < 5; q++) {
                    float2 a = un2(o2[2 * q]);
                    float2 b = un2(o2[2 * q + 1]);
                    asm volatile("red.global.add.v4.f32 [%0], {%1, %2, %3, %4};"
                                 :: "l"(op + 4 * q), "f"(a.x), "f"(a.y), "f"(b.x), "f"(b.y)
                                 : "memory");
                }
            }
        } else {
            float o = half ? 0.f : sb2[0];
#pragma unroll
            for (int cl = 0; cl < 10; cl++) o = fmaf(m[cl], sW2s[c0 + cl], o);
            o += __shfl_xor_sync(0xFFFFFFFFu, o, 1);
            if (act && half == 0)
                asm volatile("red.global.add.f32 [%0], %1;" :: "l"(out + t), "f"(o) : "memory");
        }
    }
}

// ---------------- launcher ----------------------------------------------------
extern "C" void kernel_launch(void* const* d_in, const int* in_sizes, int n_in,
                              void* d_out, int out_size) {
    const float* feat  = (const float*)d_in[0];
    const void*  edges = d_in[1];
    int E = in_sizes[1] / 2;
    if (E > EMAX) E = EMAX;

    const float* prm[27];
    for (int i = 0; i < 27; i++) prm[i] = (const float*)d_in[i];
    // per-layer param base: d=3, h=11, o=19; order W1,b1,Wm1,bm1,Wm2,bm2,W2,b2

    float *xr, *pi, *pj, *bufA, *bufB;
    cudaGetSymbolAddress((void**)&xr, g_xr);
    cudaGetSymbolAddress((void**)&pi, g_pi);
    cudaGetSymbolAddress((void**)&pj, g_pj);
    cudaGetSymbolAddress((void**)&bufA, g_bufA);
    cudaGetSymbolAddress((void**)&bufB, g_bufB);
    float4* pi4 = (float4*)pi;
    float4* pj4 = (float4*)pj;
    float* outf = (float*)d_out;

    cudaFuncSetAttribute(edge_staged_kernel<20>,
                         cudaFuncAttributeMaxDynamicSharedMemorySize, SMEM_TOT);
    cudaFuncSetAttribute(edge_staged_kernel<1>,
                         cudaFuncAttributeMaxDynamicSharedMemorySize, SMEM_TOT);

    const int TB = 256;
    int gn20 = (NNODES * 105 + TB - 1) / TB;   // node: C_OUT = 20
    int gn1  = (NNODES * 101 + TB - 1) / TB;   // node: C_OUT = 1
    int gnd  = (NNODES + TB - 1) / TB;
    int ge   = (E + TB - 1) / TB;
    int ntiles = (E + TE - 1) / TE;
    int gst = 3 * 148; if (gst > ntiles) gst = ntiles;

    detect_kernel<<<1, 32>>>((const int*)edges, 2 * E);
    convert_kernel<<<ge, TB>>>(edges, E);

    // layer d: 1 -> 20
    node_d_kernel<<<gnd, TB>>>(feat, prm[3], prm[4], xr, bufA);
    edge_d_kernel<<<ge, TB>>>(E, xr, prm[5], prm[6], prm[7], prm[8], prm[9], prm[10], bufA);

    // 3x layer h: 20 -> 20
    node_kernel<20><<<gn20, TB>>>(bufA, prm[11], prm[12], prm[13], prm[14],
                                  xr, pi4, pj4, bufB);
    edge_staged_kernel<20><<<gst, TB, SMEM_TOT>>>(E, ntiles, xr, pi4, pj4,
                                                  prm[15], prm[16], prm[17], prm[18], bufB);

    node_kernel<20><<<gn20, TB>>>(bufB, prm[11], prm[12], prm[13], prm[14],
                                  xr, pi4, pj4, bufA);
    edge_staged_kernel<20><<<gst, TB, SMEM_TOT>>>(E, ntiles, xr, pi4, pj4,
                                                  prm[15], prm[16], prm[17], prm[18], bufA);

    node_kernel<20><<<gn20, TB>>>(bufA, prm[11], prm[12], prm[13], prm[14],
                                  xr, pi4, pj4, bufB);
    edge_staged_kernel<20><<<gst, TB, SMEM_TOT>>>(E, ntiles, xr, pi4, pj4,
                                                  prm[15], prm[16], prm[17], prm[18], bufB);

    // layer o: 20 -> 1
    node_kernel<1><<<gn1, TB>>>(bufB, prm[19], prm[20], prm[21], prm[22],
                                xr, pi4, pj4, outf);
    edge_staged_kernel<1><<<gst, TB, SMEM_TOT>>>(E, ntiles, xr, pi4, pj4,
                                                 prm[23], prm[24], prm[25], prm[26], outf);
}

// round 11
// speedup vs baseline: 1.3708x; 1.0099x over previous
#include <cuda_runtime.h>

typedef unsigned long long u64;

#define NNODES 25000
#define CMSG   200
#define EMAX   400000

// ---------------- scratch (no allocation allowed -> device globals) ----------
static __device__ float g_xr[NNODES * 20];
static __device__ float g_pi[NNODES * CMSG];
static __device__ float g_pj[NNODES * CMSG];
static __device__ float g_bufA[NNODES * 20];
static __device__ float g_bufB[NNODES * 20];
static __device__ int   g_src[EMAX];
static __device__ int   g_dst[EMAX];
static __device__ int   g_is64;

// ---------------- packed fp32x2 helpers --------------------------------------
__device__ __forceinline__ u64 pack2(float lo, float hi) {
    u64 r; asm("mov.b64 %0, {%1, %2};" : "=l"(r) : "f"(lo), "f"(hi)); return r;
}
__device__ __forceinline__ u64 packbb(float v) { return pack2(v, v); }
__device__ __forceinline__ void fma2(u64& d, u64 a, u64 b) {
    asm("fma.rn.f32x2 %0, %1, %2, %0;" : "+l"(d) : "l"(a), "l"(b));
}
__device__ __forceinline__ void add2(u64& d, u64 a) {
    asm("add.rn.f32x2 %0, %0, %1;" : "+l"(d) : "l"(a));
}
__device__ __forceinline__ float2 un2(u64 v) {
    float2 f; asm("mov.b64 {%0, %1}, %2;" : "=f"(f.x), "=f"(f.y) : "l"(v)); return f;
}

// ---------------- edge index normalization (parallel detect) -----------------
__global__ void detect_kernel(const int* __restrict__ edges_raw, int n32) {
    int lane = threadIdx.x;             // 32 threads
    int idx = 2 * lane + 1;             // high words of first 32 int64 slots
    int v = (idx < n32) ? edges_raw[idx] : 0;
    unsigned nzmask = __ballot_sync(0xFFFFFFFFu, v != 0);
    if (lane == 0) g_is64 = (nzmask == 0) ? 1 : 0;
}

__global__ void convert_kernel(const void* __restrict__ edges_raw, int E) {
    int e = blockIdx.x * blockDim.x + threadIdx.x;
    if (e >= E) return;
    if (g_is64) {
        const long long* p = (const long long*)edges_raw;
        g_src[e] = (int)p[e];
        g_dst[e] = (int)p[E + e];
    } else {
        const int* p = (const int*)edges_raw;
        g_src[e] = p[e];
        g_dst[e] = p[E + e];
    }
}

// ---------------- d-layer node kernel ----------------------------------------
__global__ void node_d_kernel(const float* __restrict__ feat,
                              const float* __restrict__ W1, const float* __restrict__ b1,
                              float* __restrict__ xr, float* __restrict__ out) {
    int n = blockIdx.x * blockDim.x + threadIdx.x;
    if (n >= NNODES) return;
    float x = __ldg(feat + n);
    xr[n] = x;
    float4* o4 = reinterpret_cast<float4*>(out + n * 20);
    const float4* w4 = reinterpret_cast<const float4*>(W1);
    const float4* b4 = reinterpret_cast<const float4*>(b1);
#pragma unroll
    for (int g = 0; g < 5; g++) {
        float4 w = __ldg(w4 + g);
        float4 b = __ldg(b4 + g);
        o4[g] = make_float4(fmaf(x, w.x, b.x), fmaf(x, w.y, b.y),
                            fmaf(x, w.z, b.z), fmaf(x, w.w, b.w));
    }
}

// ---------------- generic node precompute (C_IN = 20) ------------------------
// One thread computes BOTH pi4[n][g] and pj4[n][g] (same x row, 40 weight
// loads) -> halves thread count and x reloads vs split pi/pj threads.
template <int C_OUT>
__global__ void node_kernel(const float* __restrict__ xin,
                            const float* __restrict__ W1, const float* __restrict__ b1,
                            const float* __restrict__ Wm1, const float* __restrict__ bm1,
                            float* __restrict__ xr,
                            float4* __restrict__ pi4, float4* __restrict__ pj4,
                            float* __restrict__ outbuf) {
    constexpr int C_IN = 20;
    constexpr int K4   = CMSG / 4;            // 50
    constexpr int GL   = (C_OUT + 3) / 4;
    constexpr int TOTG = K4 + GL;             // 55 or 51
    int idx = blockIdx.x * blockDim.x + threadIdx.x;
    if (idx >= NNODES * TOTG) return;
    int n = idx / TOTG;
    int g = idx - n * TOTG;

    float xv[C_IN];
    {
        const float4* x4 = reinterpret_cast<const float4*>(xin + (long)n * C_IN);
#pragma unroll
        for (int q = 0; q < C_IN / 4; q++) {
            float4 v = __ldg(x4 + q);
            xv[4 * q + 0] = fmaxf(v.x, 0.f);
            xv[4 * q + 1] = fmaxf(v.y, 0.f);
            xv[4 * q + 2] = fmaxf(v.z, 0.f);
            xv[4 * q + 3] = fmaxf(v.w, 0.f);
        }
    }
    if (g == 0) {
        float4* xr4 = reinterpret_cast<float4*>(xr + (long)n * C_IN);
#pragma unroll
        for (int q = 0; q < C_IN / 4; q++)
            xr4[q] = make_float4(xv[4 * q], xv[4 * q + 1], xv[4 * q + 2], xv[4 * q + 3]);
    }

    if (g < K4) {
        const float4* W4 = reinterpret_cast<const float4*>(Wm1);  // [2*C_IN][K4]
        float4 ai = __ldg(reinterpret_cast<const float4*>(bm1) + g);
        float4 aj = make_float4(0.f, 0.f, 0.f, 0.f);
#pragma unroll
        for (int c = 0; c < C_IN; c++) {
            float4 wi = __ldg(W4 + c * K4 + g);
            ai.x = fmaf(xv[c], wi.x, ai.x);
            ai.y = fmaf(xv[c], wi.y, ai.y);
            ai.z = fmaf(xv[c], wi.z, ai.z);
            ai.w = fmaf(xv[c], wi.w, ai.w);
            float4 wj = __ldg(W4 + (C_IN + c) * K4 + g);
            aj.x = fmaf(xv[c], wj.x, aj.x);
            aj.y = fmaf(xv[c], wj.y, aj.y);
            aj.z = fmaf(xv[c], wj.z, aj.z);
            aj.w = fmaf(xv[c], wj.w, aj.w);
        }
        pi4[(long)n * K4 + g] = ai;
        pj4[(long)n * K4 + g] = aj;
    } else {
        int gl = g - K4;
        if constexpr (C_OUT % 4 == 0) {
            float4 acc = __ldg(reinterpret_cast<const float4*>(b1) + gl);
#pragma unroll
            for (int c = 0; c < C_IN; c++) {
                float4 w = __ldg(reinterpret_cast<const float4*>(W1) + c * (C_OUT / 4) + gl);
                acc.x = fmaf(xv[c], w.x, acc.x);
                acc.y = fmaf(xv[c], w.y, acc.y);
                acc.z = fmaf(xv[c], w.z, acc.z);
                acc.w = fmaf(xv[c], w.w, acc.w);
            }
            reinterpret_cast<float4*>(outbuf)[(long)n * (C_OUT / 4) + gl] = acc;
        } else {
#pragma unroll
            for (int k = gl * 4; k < C_OUT && k < gl * 4 + 4; k++) {
                float o = __ldg(b1 + k);
#pragma unroll
                for (int c = 0; c < C_IN; c++)
                    o = fmaf(xv[c], __ldg(W1 + c * C_OUT + k), o);
                outbuf[(long)n * C_OUT + k] = o;
            }
        }
    }
}

// ---------------- d-layer edge kernel (C_IN = 1) ------------------------------
__global__ void __launch_bounds__(256)
edge_d_kernel(int E, const float* __restrict__ xr,
              const float* __restrict__ Wm1, const float* __restrict__ bm1,
              const float* __restrict__ Wm2, const float* __restrict__ bm2,
              const float* __restrict__ W2, const float* __restrict__ b2,
              float* __restrict__ out) {
    __shared__ float4 sA[50], sB[50], sbm[50], sw[50];
    __shared__ float sW2v[20], sb2v[20];
    __shared__ float sbm2;
    int tid = threadIdx.x;
    if (tid < 50) {
        sA[tid]  = __ldg(reinterpret_cast<const float4*>(Wm1) + tid);
        sB[tid]  = __ldg(reinterpret_cast<const float4*>(Wm1 + CMSG) + tid);
        sbm[tid] = __ldg(reinterpret_cast<const float4*>(bm1) + tid);
        sw[tid]  = __ldg(reinterpret_cast<const float4*>(Wm2) + tid);
    }
    if (tid < 20) { sW2v[tid] = W2[tid]; sb2v[tid] = b2[tid]; }
    if (tid == 0) sbm2 = bm2[0];
    __syncthreads();

    int e = blockIdx.x * blockDim.x + tid;
    if (e >= E) return;
    int s = g_src[e], t = g_dst[e];
    float xi = __ldg(xr + t);
    float xj = __ldg(xr + s);

    float gate = sbm2;
#pragma unroll 2
    for (int k = 0; k < 50; k++) {
        float4 A = sA[k], B = sB[k], bm = sbm[k], w = sw[k];
        float h0 = fmaxf(fmaf(xi, A.x, fmaf(xj, B.x, bm.x)), 0.f);
        float h1 = fmaxf(fmaf(xi, A.y, fmaf(xj, B.y, bm.y)), 0.f);
        float h2 = fmaxf(fmaf(xi, A.z, fmaf(xj, B.z, bm.z)), 0.f);
        float h3 = fmaxf(fmaf(xi, A.w, fmaf(xj, B.w, bm.w)), 0.f);
        gate = fmaf(h0, w.x, gate);
        gate = fmaf(h1, w.y, gate);
        gate = fmaf(h2, w.z, gate);
        gate = fmaf(h3, w.w, gate);
    }

    float m = gate * (xi - xj);
    float* op = out + (long)t * 20;
#pragma unroll
    for (int co = 0; co < 20; co += 4) {
        float o0 = fmaf(m, sW2v[co],     sb2v[co]);
        float o1 = fmaf(m, sW2v[co + 1], sb2v[co + 1]);
        float o2 = fmaf(m, sW2v[co + 2], sb2v[co + 2]);
        float o3 = fmaf(m, sW2v[co + 3], sb2v[co + 3]);
        asm volatile("red.global.add.v4.f32 [%0], {%1, %2, %3, %4};"
                     :: "l"(op + co), "f"(o0), "f"(o1), "f"(o2), "f"(o3) : "memory");
    }
}

// ---------------- staged edge kernel (C_IN = 20, f32 gathers) -----------------
// Pass 1 (per k-chunk): 256 threads cooperatively gather pi/pj rows for 128
// edges (coalesced LDG.128) and store h = relu(pi+pj) into smem.
// Pass 2: 2 threads per edge, each owns 10 gate channels (f32x2 pairs);
// msg partials combined via shfl_xor; half 0 issues REDs.
#define TE     128
#define KCH    25   // float4 per chunk (100 floats); 2 chunks
#define OFF_HBUF  0
#define SZ_HBUF   (TE * KCH * 16)           // 51200
#define OFF_WM2P  (OFF_HBUF + SZ_HBUF)      // 51200
#define SZ_WM2P   (CMSG * 24 * 4)           // 19200 (rows padded 20 -> 24, gap at 10)
#define OFF_W2S   (OFF_WM2P + SZ_WM2P)      // 70400
#define SZ_W2S    (20 * 20 * 4)
#define OFF_BM2   (OFF_W2S + SZ_W2S)        // 72000
#define OFF_B2    (OFF_BM2 + 96)            // 72096
#define OFF_SRC   (OFF_B2 + 96)             // 72192
#define OFF_DST   (OFF_SRC + TE * 4)        // 72704
#define SMEM_TOT  (OFF_DST + TE * 4)        // 73216

template <int C_OUT>
__global__ void __launch_bounds__(256)
edge_staged_kernel(int E, int ntiles,
                   const float* __restrict__ xr,
                   const float4* __restrict__ pi4, const float4* __restrict__ pj4,
                   const float* __restrict__ Wm2, const float* __restrict__ bm2,
                   const float* __restrict__ W2, const float* __restrict__ b2,
                   float* __restrict__ out) {
    extern __shared__ char dyn[];
    float4* hbuf4 = reinterpret_cast<float4*>(dyn + OFF_HBUF);
    float*  sWm2p = reinterpret_cast<float*>(dyn + OFF_WM2P);
    float*  sW2s  = reinterpret_cast<float*>(dyn + OFF_W2S);
    float*  sbm2  = reinterpret_cast<float*>(dyn + OFF_BM2);
    float*  sb2   = reinterpret_cast<float*>(dyn + OFF_B2);
    int*    ssrc  = reinterpret_cast<int*>(dyn + OFF_SRC);
    int*    sdst  = reinterpret_cast<int*>(dyn + OFF_DST);

    int tid = threadIdx.x;
    // weights once per block
    for (int i = tid; i < CMSG * 20; i += 256) {
        int k = i / 20, c = i - k * 20;
        sWm2p[k * 24 + c + ((c >= 10) ? 2 : 0)] = Wm2[i];
    }
    for (int i = tid; i < 20 * C_OUT; i += 256) sW2s[i] = W2[i];
    if (tid < 20) sbm2[tid] = bm2[tid];
    if (tid < C_OUT) sb2[tid] = b2[tid];

    int eloc = tid >> 1;
    int half = tid & 1;
    int c0 = half * 10;

    for (int tile = blockIdx.x; tile < ntiles; tile += gridDim.x) {
        int e0 = tile * TE;
        int tileE = E - e0; if (tileE > TE) tileE = TE;

        __syncthreads();   // protect ssrc/hbuf from previous tile readers
        for (int i = tid; i < TE; i += 256) {
            int e = e0 + ((i < tileE) ? i : (tileE - 1));
            ssrc[i] = g_src[e];
            sdst[i] = g_dst[e];
        }
        __syncthreads();

        bool act = (eloc < tileE);
        int s = ssrc[eloc];
        int t = sdst[eloc];

        u64 gate2[5];
#pragma unroll
        for (int p = 0; p < 5; p++) gate2[p] = pack2(sbm2[c0 + 2 * p], sbm2[c0 + 2 * p + 1]);

#pragma unroll
        for (int ch = 0; ch < 2; ch++) {
            // ---- stage chunk: coalesced gather + relu ----
#pragma unroll 1
            for (int slot = tid; slot < TE * KCH; slot += 256) {
                int e = slot / KCH;
                int k4 = slot - e * KCH;
                if (e < tileE) {
                    int kg = ch * KCH + k4;
                    float4 a = __ldg(pi4 + (long)sdst[e] * 50 + kg);
                    float4 b = __ldg(pj4 + (long)ssrc[e] * 50 + kg);
                    float4 h;
                    h.x = fmaxf(a.x + b.x, 0.f);
                    h.y = fmaxf(a.y + b.y, 0.f);
                    h.z = fmaxf(a.z + b.z, 0.f);
                    h.w = fmaxf(a.w + b.w, 0.f);
                    hbuf4[e * KCH + k4] = h;
                }
            }
            __syncthreads();
            // ---- accumulate gates for own edge/half ----
#pragma unroll 1
            for (int k4 = 0; k4 < KCH; k4++) {
                float4 h = hbuf4[eloc * KCH + k4];
                const float* wbase = sWm2p + (ch * KCH + k4) * 4 * 24 + half * 12;
                float hs[4] = {h.x, h.y, h.z, h.w};
#pragma unroll
                for (int j = 0; j < 4; j++) {
                    u64 hb = packbb(hs[j]);
                    const ulonglong2* wr = reinterpret_cast<const ulonglong2*>(wbase + j * 24);
                    ulonglong2 w0 = wr[0];
                    fma2(gate2[0], hb, w0.x);
                    fma2(gate2[1], hb, w0.y);
                    ulonglong2 w1 = wr[1];
                    fma2(gate2[2], hb, w1.x);
                    fma2(gate2[3], hb, w1.y);
                    u64 w2v = *reinterpret_cast<const u64*>(wbase + j * 24 + 8);
                    fma2(gate2[4], hb, w2v);
                }
            }
            __syncthreads();
        }

        // ---- msg + scatter ----
        float m[10];
        {
            const float2* xt2 = reinterpret_cast<const float2*>(xr + (long)t * 20 + c0);
            const float2* xs2 = reinterpret_cast<const float2*>(xr + (long)s * 20 + c0);
#pragma unroll
            for (int p = 0; p < 5; p++) {
                float2 xt = __ldg(xt2 + p);
                float2 xs = __ldg(xs2 + p);
                float2 g = un2(gate2[p]);
                m[2 * p]     = g.x * (xt.x - xs.x);
                m[2 * p + 1] = g.y * (xt.y - xs.y);
            }
        }

        if constexpr (C_OUT == 20) {
            u64 o2[10];
#pragma unroll
            for (int p = 0; p < 10; p++)
                o2[p] = half ? 0ULL : pack2(sb2[2 * p], sb2[2 * p + 1]);
#pragma unroll
            for (int cl = 0; cl < 10; cl++) {
                u64 mb = packbb(m[cl]);
                const ulonglong2* wr =
                    reinterpret_cast<const ulonglong2*>(sW2s + (c0 + cl) * 20);
#pragma unroll
                for (int q = 0; q < 5; q++) {
                    ulonglong2 w = wr[q];
                    fma2(o2[2 * q], mb, w.x);
                    fma2(o2[2 * q + 1], mb, w.y);
                }
            }
#pragma unroll
            for (int p = 0; p < 10; p++) {
                u64 other = __shfl_xor_sync(0xFFFFFFFFu, o2[p], 1);
                add2(o2[p], other);
            }
            if (act && half == 0) {
                float* op = out + (long)t * 20;
#pragma unroll
                for (int q = 0; q < 5; q++) {
                    float2 a = un2(o2[2 * q]);
                    float2 b = un2(o2[2 * q + 1]);
                    asm volatile("red.global.add.v4.f32 [%0], {%1, %2, %3, %4};"
                                 :: "l"(op + 4 * q), "f"(a.x), "f"(a.y), "f"(b.x), "f"(b.y)
                                 : "memory");
                }
            }
        } else {
            float o = half ? 0.f : sb2[0];
#pragma unroll
            for (int cl = 0; cl < 10; cl++) o = fmaf(m[cl], sW2s[c0 + cl], o);
            o += __shfl_xor_sync(0xFFFFFFFFu, o, 1);
            if (act && half == 0)
                asm volatile("red.global.add.f32 [%0], %1;" :: "l"(out + t), "f"(o) : "memory");
        }
    }
}

// ---------------- launcher ----------------------------------------------------
extern "C" void kernel_launch(void* const* d_in, const int* in_sizes, int n_in,
                              void* d_out, int out_size) {
    const float* feat  = (const float*)d_in[0];
    const void*  edges = d_in[1];
    int E = in_sizes[1] / 2;
    if (E > EMAX) E = EMAX;

    const float* prm[27];
    for (int i = 0; i < 27; i++) prm[i] = (const float*)d_in[i];
    // per-layer param base: d=3, h=11, o=19; order W1,b1,Wm1,bm1,Wm2,bm2,W2,b2

    float *xr, *pi, *pj, *bufA, *bufB;
    cudaGetSymbolAddress((void**)&xr, g_xr);
    cudaGetSymbolAddress((void**)&pi, g_pi);
    cudaGetSymbolAddress((void**)&pj, g_pj);
    cudaGetSymbolAddress((void**)&bufA, g_bufA);
    cudaGetSymbolAddress((void**)&bufB, g_bufB);
    float4* pi4 = (float4*)pi;
    float4* pj4 = (float4*)pj;
    float* outf = (float*)d_out;

    cudaFuncSetAttribute(edge_staged_kernel<20>,
                         cudaFuncAttributeMaxDynamicSharedMemorySize, SMEM_TOT);
    cudaFuncSetAttribute(edge_staged_kernel<1>,
                         cudaFuncAttributeMaxDynamicSharedMemorySize, SMEM_TOT);

    const int TB = 256;
    int gn20 = (NNODES * 55 + TB - 1) / TB;    // node: C_OUT = 20 (TOTG=55)
    int gn1  = (NNODES * 51 + TB - 1) / TB;    // node: C_OUT = 1  (TOTG=51)
    int gnd  = (NNODES + TB - 1) / TB;
    int ge   = (E + TB - 1) / TB;
    int ntiles = (E + TE - 1) / TE;
    int gst = 3 * 148; if (gst > ntiles) gst = ntiles;

    detect_kernel<<<1, 32>>>((const int*)edges, 2 * E);
    convert_kernel<<<ge, TB>>>(edges, E);

    // layer d: 1 -> 20
    node_d_kernel<<<gnd, TB>>>(feat, prm[3], prm[4], xr, bufA);
    edge_d_kernel<<<ge, TB>>>(E, xr, prm[5], prm[6], prm[7], prm[8], prm[9], prm[10], bufA);

    // 3x layer h: 20 -> 20
    node_kernel<20><<<gn20, TB>>>(bufA, prm[11], prm[12], prm[13], prm[14],
                                  xr, pi4, pj4, bufB);
    edge_staged_kernel<20><<<gst, TB, SMEM_TOT>>>(E, ntiles, xr, pi4, pj4,
                                                  prm[15], prm[16], prm[17], prm[18], bufB);

    node_kernel<20><<<gn20, TB>>>(bufB, prm[11], prm[12], prm[13], prm[14],
                                  xr, pi4, pj4, bufA);
    edge_staged_kernel<20><<<gst, TB, SMEM_TOT>>>(E, ntiles, xr, pi4, pj4,
                                                  prm[15], prm[16], prm[17], prm[18], bufA);

    node_kernel<20><<<gn20, TB>>>(bufA, prm[11], prm[12], prm[13], prm[14],
                                  xr, pi4, pj4, bufB);
    edge_staged_kernel<20><<<gst, TB, SMEM_TOT>>>(E, ntiles, xr, pi4, pj4,
                                                  prm[15], prm[16], prm[17], prm[18], bufB);

    // layer o: 20 -> 1
    node_kernel<1><<<gn1, TB>>>(bufB, prm[19], prm[20], prm[21], prm[22],
                                xr, pi4, pj4, outf);
    edge_staged_kernel<1><<<gst, TB, SMEM_TOT>>>(E, ntiles, xr, pi4, pj4,
                                                 prm[23], prm[24], prm[25], prm[26], outf);
}